// round 3
// baseline (speedup 1.0000x reference)
#include <cuda_runtime.h>
#include <cuda_bf16.h>

// Problem constants (fixed by the dataset)
#define NN 50000
#define NE 600000
#define DD 128
#define NC 64

// ---------------- scratch (no allocations allowed) ----------------
__device__ float g_xw[NN * DD];        // X @ W
__device__ int   g_deg[NN];            // intra in-degree counts
__device__ float g_dinv[NN];           // rsqrt(deg+1)
__device__ int   g_cluster_edges[NC];  // intra-edge count per cluster
__device__ int   g_intra_src[NE];
__device__ int   g_intra_dst[NE];
__device__ int   g_intra_count;

// ---------------- kernel 1: zero counters ----------------
__global__ void zero_kernel() {
    int i = blockIdx.x * blockDim.x + threadIdx.x;
    if (i < NN) g_deg[i] = 0;
    if (i < NC) g_cluster_edges[i] = 0;
    if (i == 0) g_intra_count = 0;
}

// ---------------- kernel 2: GEMM  XW = X @ W ----------------
// blockDim = 128 (4 warps). Each block: 32 rows.
// smem: W full (128x128 f32 = 64KB) + Xs (32x128 f32 = 16KB) = 80KB dynamic.
// Warp w owns rows [w*8, w*8+8); lane owns cols [lane*4, lane*4+4).
__global__ void gemm_kernel(const float* __restrict__ X,
                            const float* __restrict__ W,
                            int n) {
    extern __shared__ float smem[];
    float* Ws = smem;              // 16384 floats
    float* Xs = smem + DD * DD;    // 4096 floats

    const int tid  = threadIdx.x;
    const int warp = tid >> 5;
    const int lane = tid & 31;
    const int row0 = blockIdx.x * 32;

    // Load W (float4, coalesced)
    float4* Ws4 = (float4*)Ws;
    const float4* W4 = (const float4*)W;
    #pragma unroll
    for (int i = tid; i < DD * DD / 4; i += 128) Ws4[i] = W4[i];

    // Load 32 rows of X (zero-pad OOB rows)
    float4* Xs4 = (float4*)Xs;
    const float4* X4 = (const float4*)X;
    #pragma unroll
    for (int i = tid; i < 32 * DD / 4; i += 128) {
        int r  = i >> 5;           // 32 float4 per row
        int c4 = i & 31;
        int row = row0 + r;
        Xs4[i] = (row < n) ? X4[row * 32 + c4]
                           : make_float4(0.f, 0.f, 0.f, 0.f);
    }
    __syncthreads();

    float acc[8][4];
    #pragma unroll
    for (int r = 0; r < 8; r++)
        #pragma unroll
        for (int c = 0; c < 4; c++) acc[r][c] = 0.f;

    const int rbase = warp * 8;
    #pragma unroll 4
    for (int k = 0; k < DD; k++) {
        float4 wv = Ws4[k * 32 + lane];
        #pragma unroll
        for (int r = 0; r < 8; r++) {
            float xv = Xs[(rbase + r) * DD + k];
            acc[r][0] = fmaf(xv, wv.x, acc[r][0]);
            acc[r][1] = fmaf(xv, wv.y, acc[r][1]);
            acc[r][2] = fmaf(xv, wv.z, acc[r][2]);
            acc[r][3] = fmaf(xv, wv.w, acc[r][3]);
        }
    }

    float4* XW4 = (float4*)g_xw;
    #pragma unroll
    for (int r = 0; r < 8; r++) {
        int row = row0 + rbase + r;
        if (row < n)
            XW4[row * 32 + lane] =
                make_float4(acc[r][0], acc[r][1], acc[r][2], acc[r][3]);
    }
}

// ---------------- kernel 3: edge pass (mask + degree + compact) ----------------
__global__ void edge_pass_kernel(const int* __restrict__ ei,
                                 const int* __restrict__ cl,
                                 int E) {
    int e = blockIdx.x * blockDim.x + threadIdx.x;
    if (e >= E) return;
    int s = ei[e];
    int d = ei[E + e];
    int cs = cl[s];
    if (cs == cl[d]) {
        atomicAdd(&g_deg[d], 1);
        atomicAdd(&g_cluster_edges[cs], 1);
        int p = atomicAdd(&g_intra_count, 1);
        g_intra_src[p] = s;
        g_intra_dst[p] = d;
    }
}

// ---------------- kernel 4: node pass (dinv + init out) ----------------
// one thread per (node, float4-column): NN*32 threads.
__global__ void node_pass_kernel(const float* __restrict__ X,
                                 const float* __restrict__ b,
                                 const int* __restrict__ cl,
                                 float* __restrict__ out,
                                 int n) {
    int idx = blockIdx.x * blockDim.x + threadIdx.x;
    if (idx >= n * 32) return;
    int node = idx >> 5;
    int c4   = idx & 31;

    int   icnt = g_deg[node];
    float deg  = (float)icnt + 1.0f;
    if (c4 == 0) g_dinv[node] = rsqrtf(deg);

    bool has = g_cluster_edges[cl[node]] > 0;

    float4 o;
    if (has) {
        float4 xw = ((const float4*)g_xw)[idx];
        float4 bb = ((const float4*)b)[c4];
        float inv = 1.0f / deg;
        o.x = fmaf(xw.x, inv, bb.x);
        o.y = fmaf(xw.y, inv, bb.y);
        o.z = fmaf(xw.z, inv, bb.z);
        o.w = fmaf(xw.w, inv, bb.w);
    } else {
        o = ((const float4*)X)[idx];
    }
    ((float4*)out)[idx] = o;
}

// ---------------- kernel 5: scatter over compacted intra edges ----------------
// one warp per intra edge; lane handles one float4 (4 scalar atomics).
__global__ void scatter_kernel(float* __restrict__ out) {
    int cnt  = g_intra_count;
    int gtid = blockIdx.x * blockDim.x + threadIdx.x;
    int warp = gtid >> 5;
    int lane = gtid & 31;
    int nw   = (gridDim.x * blockDim.x) >> 5;

    for (int e = warp; e < cnt; e += nw) {
        int s = g_intra_src[e];
        int d = g_intra_dst[e];
        float w = g_dinv[s] * g_dinv[d];
        float4 v = ((const float4*)(g_xw + s * DD))[lane];
        float* o = out + d * DD + lane * 4;
        atomicAdd(o + 0, w * v.x);
        atomicAdd(o + 1, w * v.y);
        atomicAdd(o + 2, w * v.z);
        atomicAdd(o + 3, w * v.w);
    }
}

// ---------------- launch ----------------
extern "C" void kernel_launch(void* const* d_in, const int* in_sizes, int n_in,
                              void* d_out, int out_size) {
    const float* X  = (const float*)d_in[0];
    const float* W  = (const float*)d_in[1];
    const float* b  = (const float*)d_in[2];
    // d_in[3] = edge_attr (unused)
    const int* cl = (const int*)d_in[4];
    const int* ei = (const int*)d_in[5];
    float* out = (float*)d_out;

    const int N = in_sizes[4];
    const int E = in_sizes[3];

    // GEMM needs 80KB dynamic smem (> 48KB default) — opt in every call (idempotent).
    static const size_t GEMM_SMEM = (size_t)(DD * DD + 32 * DD) * sizeof(float);
    cudaFuncSetAttribute(gemm_kernel,
                         cudaFuncAttributeMaxDynamicSharedMemorySize,
                         (int)GEMM_SMEM);

    // 1. zero counters
    {
        int total = NN;  // covers NN, NC, and the single counter
        zero_kernel<<<(total + 255) / 256, 256>>>();
    }
    // 2. GEMM
    {
        int blocks = (N + 31) / 32;
        gemm_kernel<<<blocks, 128, GEMM_SMEM>>>(X, W, N);
    }
    // 3. edge pass
    edge_pass_kernel<<<(E + 255) / 256, 256>>>(ei, cl, E);
    // 4. node pass
    {
        int total = N * 32;
        node_pass_kernel<<<(total + 255) / 256, 256>>>(X, b, cl, out, N);
    }
    // 5. scatter
    scatter_kernel<<<512, 256>>>(out);
}

// round 5
// speedup vs baseline: 1.6842x; 1.6842x over previous
#include <cuda_runtime.h>
#include <cuda_bf16.h>
#include <cstdint>

#define NN 50000
#define NE 600000
#define DD 128
#define NC 64
#define SWIDE 136   // padded row stride in bf16 elems (272B) -> conflict-free frags

// ---------------- scratch (no allocations allowed) ----------------
__device__ float g_xw[NN * DD];
__device__ int   g_deg[NN];
__device__ float g_dinv[NN];
__device__ int   g_cluster_edges[NC];
__device__ int   g_intra_src[NE];
__device__ int   g_intra_dst[NE];
__device__ int   g_intra_count;
// W^T hi/lo in padded row-major [n][k] (row stride SWIDE)
__device__ __align__(16) __nv_bfloat16 g_wthi[DD * SWIDE];
__device__ __align__(16) __nv_bfloat16 g_wtlo[DD * SWIDE];

__device__ __forceinline__ void split_bf16(float v, __nv_bfloat16& h, __nv_bfloat16& l) {
    h = __float2bfloat16(v);
    l = __float2bfloat16(v - __bfloat162float(h));
}
__device__ __forceinline__ uint32_t pack2(__nv_bfloat16 a, __nv_bfloat16 b) {
    __nv_bfloat162 t; t.x = a; t.y = b;
    return *reinterpret_cast<uint32_t*>(&t);
}
__device__ __forceinline__ void mma16816(float c[4], const uint32_t a[4],
                                         uint32_t b0, uint32_t b1) {
    asm volatile(
        "mma.sync.aligned.m16n8k16.row.col.f32.bf16.bf16.f32 "
        "{%0,%1,%2,%3}, {%4,%5,%6,%7}, {%8,%9}, {%0,%1,%2,%3};"
        : "+f"(c[0]), "+f"(c[1]), "+f"(c[2]), "+f"(c[3])
        : "r"(a[0]), "r"(a[1]), "r"(a[2]), "r"(a[3]), "r"(b0), "r"(b1));
}

// ---------------- kernel 1: zero counters ----------------
__global__ void zero_kernel() {
    int i = blockIdx.x * blockDim.x + threadIdx.x;
    if (i < NN) g_deg[i] = 0;
    if (i < NC) g_cluster_edges[i] = 0;
    if (i == 0) g_intra_count = 0;
}

// ---------------- kernel 2: W^T bf16 hi/lo, padded row-major ----------------
__global__ void wprep_kernel(const float* __restrict__ W) {
    int i = blockIdx.x * blockDim.x + threadIdx.x;
    if (i >= DD * DD) return;
    int nrow = i >> 7;
    int k = i & 127;
    float v = W[k * DD + nrow];
    __nv_bfloat16 h, l;
    split_bf16(v, h, l);
    g_wthi[nrow * SWIDE + k] = h;
    g_wtlo[nrow * SWIDE + k] = l;
}

// ---------------- kernel 3: edge pass (mask + degree + warp-agg compact) ----
__global__ void edge_pass_kernel(const int* __restrict__ ei,
                                 const int* __restrict__ cl,
                                 int E) {
    int e = blockIdx.x * blockDim.x + threadIdx.x;
    int s = 0, d = 0, cs = 0;
    bool intra = false;
    if (e < E) {
        s = ei[e];
        d = ei[E + e];
        cs = cl[s];
        intra = (cs == cl[d]);
    }
    unsigned mask = __ballot_sync(0xFFFFFFFFu, intra);
    if (intra) {
        atomicAdd(&g_deg[d], 1);
        atomicAdd(&g_cluster_edges[cs], 1);
        int lane = threadIdx.x & 31;
        int leader = __ffs(mask) - 1;
        int base = 0;
        if (lane == leader) base = atomicAdd(&g_intra_count, __popc(mask));
        base = __shfl_sync(mask, base, leader);
        int pos = base + __popc(mask & ((1u << lane) - 1u));
        g_intra_src[pos] = s;
        g_intra_dst[pos] = d;
    }
}

// ---------------- kernel 4: fused HMMA GEMM + node epilogue ----------------
// 256 threads (8 warps), CTA tile M=128 x N=128.
// Warp grid: 4 (M) x 2 (N); warp tile M=32 (2 m16), N=64 (8 n8).
// smem (bytes): bias 512 | Ahi 34816 | Alo 34816 | Whi 34816 | Wlo 34816
#define SM_B    0
#define SM_AHI  512
#define SM_ALO  (512 + 34816)
#define SM_WHI  (512 + 2 * 34816)
#define SM_WLO  (512 + 3 * 34816)
#define SM_TOT  (512 + 4 * 34816)

__global__ void __launch_bounds__(256, 1)
gemm_fused_kernel(const float* __restrict__ X,
                  const float* __restrict__ b,
                  const int* __restrict__ cl,
                  float* __restrict__ out,
                  int n) {
    extern __shared__ char smem[];
    float* bias = (float*)(smem + SM_B);
    __nv_bfloat16* Ahi = (__nv_bfloat16*)(smem + SM_AHI);
    __nv_bfloat16* Alo = (__nv_bfloat16*)(smem + SM_ALO);
    __nv_bfloat16* Whi = (__nv_bfloat16*)(smem + SM_WHI);
    __nv_bfloat16* Wlo = (__nv_bfloat16*)(smem + SM_WLO);

    const int tid  = threadIdx.x;
    const int row0 = blockIdx.x * 128;

    if (tid < 128) bias[tid] = b[tid];

    // copy padded W^T hi/lo (34816B each = 2176 uint4)
    {
        const uint4* gh = (const uint4*)g_wthi;
        const uint4* gl = (const uint4*)g_wtlo;
        uint4* sh = (uint4*)Whi;
        uint4* sl = (uint4*)Wlo;
        #pragma unroll
        for (int i = tid; i < 2176; i += 256) { sh[i] = gh[i]; sl[i] = gl[i]; }
    }

    // load X tile, split, store padded (row stride SWIDE)
    {
        const float4* X4 = (const float4*)X;
        #pragma unroll
        for (int i = tid; i < 128 * 16; i += 256) {
            int row = i >> 4;
            int c   = i & 15;          // 8-float chunk along K
            int grow = row0 + row;
            float4 a = make_float4(0.f, 0.f, 0.f, 0.f), a2 = a;
            if (grow < n) {
                a  = X4[grow * 32 + c * 2];
                a2 = X4[grow * 32 + c * 2 + 1];
            }
            float v[8] = {a.x, a.y, a.z, a.w, a2.x, a2.y, a2.z, a2.w};
            uint32_t hi[4], lo[4];
            #pragma unroll
            for (int j = 0; j < 4; j++) {
                __nv_bfloat16 h0, l0, h1, l1;
                split_bf16(v[2 * j], h0, l0);
                split_bf16(v[2 * j + 1], h1, l1);
                hi[j] = pack2(h0, h1);
                lo[j] = pack2(l0, l1);
            }
            *(uint4*)(Ahi + row * SWIDE + c * 8) = make_uint4(hi[0], hi[1], hi[2], hi[3]);
            *(uint4*)(Alo + row * SWIDE + c * 8) = make_uint4(lo[0], lo[1], lo[2], lo[3]);
        }
    }
    __syncthreads();

    const int wid  = tid >> 5;
    const int lane = tid & 31;
    const int mw   = wid & 3;     // 0..3 -> M offset mw*32
    const int nw   = wid >> 2;    // 0..1 -> N offset nw*64
    const int g    = lane >> 2;   // group 0..7
    const int tg   = lane & 3;    // 0..3

    float acc[2][8][4];
    #pragma unroll
    for (int mt = 0; mt < 2; mt++)
        #pragma unroll
        for (int nt = 0; nt < 8; nt++)
            #pragma unroll
            for (int j = 0; j < 4; j++) acc[mt][nt][j] = 0.f;

    #pragma unroll
    for (int term = 0; term < 3; term++) {
        const __nv_bfloat16* As = (term == 1) ? Alo : Ahi;
        const __nv_bfloat16* Ws = (term == 2) ? Wlo : Whi;
        #pragma unroll
        for (int ks = 0; ks < 8; ks++) {
            const int kc = ks * 16 + tg * 2;
            uint32_t a[2][4];
            #pragma unroll
            for (int mt = 0; mt < 2; mt++) {
                const __nv_bfloat16* ar = As + (mw * 32 + mt * 16 + g) * SWIDE + kc;
                a[mt][0] = *(const uint32_t*)(ar);
                a[mt][1] = *(const uint32_t*)(ar + 8 * SWIDE);
                a[mt][2] = *(const uint32_t*)(ar + 8);
                a[mt][3] = *(const uint32_t*)(ar + 8 * SWIDE + 8);
            }
            #pragma unroll
            for (int nt = 0; nt < 8; nt++) {
                const __nv_bfloat16* br = Ws + (nw * 64 + nt * 8 + g) * SWIDE + kc;
                uint32_t b0 = *(const uint32_t*)(br);
                uint32_t b1 = *(const uint32_t*)(br + 8);
                mma16816(acc[0][nt], a[0], b0, b1);
                mma16816(acc[1][nt], a[1], b0, b1);
            }
        }
    }

    // dinv for this CTA's rows
    if (tid < 128) {
        int row = row0 + tid;
        if (row < n) g_dinv[row] = rsqrtf((float)g_deg[row] + 1.0f);
    }

    // fused node epilogue: write g_xw and out from fragments
    #pragma unroll
    for (int mt = 0; mt < 2; mt++) {
        #pragma unroll
        for (int half = 0; half < 2; half++) {
            int row = row0 + mw * 32 + mt * 16 + g + half * 8;
            if (row >= n) continue;
            float deg = (float)g_deg[row] + 1.0f;
            float inv = 1.0f / deg;
            bool  has = (g_cluster_edges[cl[row]] > 0);
            #pragma unroll
            for (int nt = 0; nt < 8; nt++) {
                int ncol = nw * 64 + nt * 8 + tg * 2;
                float2 v = make_float2(acc[mt][nt][half * 2],
                                       acc[mt][nt][half * 2 + 1]);
                *(float2*)(g_xw + row * DD + ncol) = v;
                float2 o;
                if (has) {
                    o.x = fmaf(v.x, inv, bias[ncol]);
                    o.y = fmaf(v.y, inv, bias[ncol + 1]);
                } else {
                    o = *(const float2*)(X + row * DD + ncol);
                }
                *(float2*)(out + row * DD + ncol) = o;
            }
        }
    }
}

// ---------------- kernel 5: scatter over compacted intra edges --------------
__global__ void scatter_kernel(float* __restrict__ out) {
    int cnt  = g_intra_count;
    int gtid = blockIdx.x * blockDim.x + threadIdx.x;
    int warp = gtid >> 5;
    int lane = gtid & 31;
    int nw   = (gridDim.x * blockDim.x) >> 5;

    for (int e = warp; e < cnt; e += nw) {
        int s = g_intra_src[e];
        int d = g_intra_dst[e];
        float w = g_dinv[s] * g_dinv[d];
        float4 v = ((const float4*)(g_xw + s * DD))[lane];
        float* o = out + d * DD + lane * 4;
        atomicAdd(o + 0, w * v.x);
        atomicAdd(o + 1, w * v.y);
        atomicAdd(o + 2, w * v.z);
        atomicAdd(o + 3, w * v.w);
    }
}

// ---------------- launch ----------------
extern "C" void kernel_launch(void* const* d_in, const int* in_sizes, int n_in,
                              void* d_out, int out_size) {
    const float* X  = (const float*)d_in[0];
    const float* W  = (const float*)d_in[1];
    const float* b  = (const float*)d_in[2];
    // d_in[3] = edge_attr (unused)
    const int* cl = (const int*)d_in[4];
    const int* ei = (const int*)d_in[5];
    float* out = (float*)d_out;

    const int N = in_sizes[4];
    const int E = in_sizes[3];

    cudaFuncSetAttribute(gemm_fused_kernel,
                         cudaFuncAttributeMaxDynamicSharedMemorySize, SM_TOT);

    zero_kernel<<<(NN + 255) / 256, 256>>>();
    wprep_kernel<<<(DD * DD + 255) / 256, 256>>>(W);
    edge_pass_kernel<<<(E + 255) / 256, 256>>>(ei, cl, E);
    gemm_fused_kernel<<<(N + 127) / 128, 256, SM_TOT>>>(X, b, cl, out, N);
    scatter_kernel<<<512, 256>>>(out);
}